// round 10
// baseline (speedup 1.0000x reference)
#include <cuda_runtime.h>
#include <cstdint>

#define B_   8
#define OBJ_ 128
#define INP_ 64
#define HID_ 256
#define D_   192
#define ROWS_ (B_*OBJ_)   // 1024

// ---------------- device scratch (allocation-free) ----------------
__device__ __align__(256) float g_ea[ROWS_ * HID_];
__device__ __align__(256) float g_eb[ROWS_ * HID_];
__device__ __align__(256) float g_hpart[2 * ROWS_ * HID_]; // per-half pooled sums
__device__ __align__(256) float g_w12[2 * HID_ * HID_];    // tf32, frag-scrambled W1,W2
__device__ __align__(256) float g_w34[HID_ * HID_];        // w3 @ wd1 (fp32)
__device__ __align__(256) float g_b34[HID_];               // b3 @ wd1 + bd1

// ---------------- helpers ----------------
__device__ __forceinline__ uint32_t smem_u32(const void* p) {
    uint32_t a;
    asm("{ .reg .u64 t; cvta.to.shared.u64 t, %1; cvt.u32.u64 %0, t; }" : "=r"(a) : "l"(p));
    return a;
}
__device__ __forceinline__ uint32_t tf32_rna(float f) {
    uint32_t r;
    asm("cvt.rna.tf32.f32 %0, %1;" : "=r"(r) : "f"(f));
    return r;
}
__device__ __forceinline__ void mma_tf32(float d[4], const float4 a, uint32_t b0, uint32_t b1) {
    asm volatile(
        "mma.sync.aligned.m16n8k8.row.col.f32.tf32.tf32.f32 "
        "{%0,%1,%2,%3}, {%4,%5,%6,%7}, {%8,%9}, {%0,%1,%2,%3};"
        : "+f"(d[0]), "+f"(d[1]), "+f"(d[2]), "+f"(d[3])
        : "r"(__float_as_uint(a.x)), "r"(__float_as_uint(a.y)),
          "r"(__float_as_uint(a.z)), "r"(__float_as_uint(a.w)),
          "r"(b0), "r"(b1));
}
#define CP_ASYNC16(dst, src) \
    asm volatile("cp.async.cg.shared.global [%0], [%1], 16;" :: "r"(dst), "l"(src))
#define CP_COMMIT() asm volatile("cp.async.commit_group;" ::: "memory")
#define CP_WAIT(n)  asm volatile("cp.async.wait_group %0;" :: "n"(n) : "memory")

// A scrambled layout (64 rows): 16(row)x8(k) tiles of 128 floats;
// tile id = (k/8)*4 + (r/16); pos = ((r16&7)*4+(kk&3))*4 + (kk>>2)*2 + (r16>>3)
__device__ __forceinline__ int scr_pos(int r16, int kk) {
    return (((r16 & 7) << 2) + (kk & 3)) * 4 + ((kk >> 2) << 1) + (r16 >> 3);
}
__device__ __forceinline__ int scr_off(int r, int c) {
    return (((c >> 3) << 2) + (r >> 4)) * 128 + scr_pos(r & 15, c & 7);
}

#define CHK 16                 // k-rows per W chunk
#define BUFV (CHK * HID_)      // 4096 floats = 16KB per stage
#define NCHUNK (HID_ / CHK)    // 16

// ---------------------------------------------------------------------------
// Fused pre-kernel: [0,256) W1/W2 tf32-scramble; [256,513) W34=w3@wd1 (+bias);
// [513,641) encoder.
// W layout: chunk kc (16 k-rows) contiguous: off = kc*4096 + (tk*32+tn)*64 + pos
// ---------------------------------------------------------------------------
__global__ void __launch_bounds__(256) pre_kernel(
    const float* __restrict__ x0, const float* __restrict__ x1,
    const float* __restrict__ x2, const float* __restrict__ w_enc,
    const float* __restrict__ w1, const float* __restrict__ w2,
    const float* __restrict__ w3, const float* __restrict__ b3,
    const float* __restrict__ wd1, const float* __restrict__ bd1) {
    __shared__ float row[HID_];
    __shared__ float xs[8][D_];
    const int bid = blockIdx.x;
    const int tid = threadIdx.x;

    if (bid < 256) {
        int idx = bid * 256 + tid;             // k*256+n
        int k = idx >> 8, n = idx & 255;
        int kc = k >> 4, tk = (k >> 3) & 1, tn = n >> 3;
        int kk = k & 7, nn = n & 7;
        int pos = ((nn << 2) + (kk & 3)) * 2 + (kk >> 2);
        int off = kc * BUFV + (tk * 32 + tn) * 64 + pos;
        g_w12[off]               = __uint_as_float(tf32_rna(w1[idx]));
        g_w12[HID_ * HID_ + off] = __uint_as_float(tf32_rna(w2[idx]));
        return;
    }
    if (bid < 513) {
        const int m = bid - 256;               // 0..256
        row[tid] = (m < 256) ? w3[m * HID_ + tid] : b3[tid];
        __syncthreads();
        float acc = 0.f;
        float wv[8];
        #pragma unroll
        for (int q = 0; q < 8; q++) wv[q] = wd1[q * HID_ + tid];
        #pragma unroll 1
        for (int k0 = 0; k0 < HID_; k0 += 8) {
            float wnx[8];
            if (k0 + 8 < HID_) {
                #pragma unroll
                for (int q = 0; q < 8; q++) wnx[q] = wd1[(k0 + 8 + q) * HID_ + tid];
            }
            #pragma unroll
            for (int q = 0; q < 8; q++) acc = fmaf(row[k0 + q], wv[q], acc);
            #pragma unroll
            for (int q = 0; q < 8; q++) wv[q] = wnx[q];
        }
        if (m < 256) g_w34[m * HID_ + tid] = acc;
        else         g_b34[tid] = acc + bd1[tid];
        return;
    }
    // encoder: 8 rows per CTA
    const int r0 = (bid - 513) * 8;
    for (int idx = tid; idx < 8 * D_; idx += 256) {
        int r = idx / D_, d = idx % D_;
        int part = d >> 6, dd = d & 63;
        const float* src = (part == 0) ? x0 : ((part == 1) ? x1 : x2);
        xs[r][d] = src[(r0 + r) * INP_ + dd];
    }
    __syncthreads();
    float sa[8], sb[8];
    #pragma unroll
    for (int r = 0; r < 8; r++) { sa[r] = 0.f; sb[r] = 0.f; }
    #pragma unroll 1
    for (int d0 = 0; d0 < D_; d0 += 4) {
        float wa[4], wb[4];
        #pragma unroll
        for (int q = 0; q < 4; q++) {
            wa[q] = w_enc[(d0 + q) * HID_ + tid];
            wb[q] = w_enc[(D_ + d0 + q) * HID_ + tid];
        }
        #pragma unroll
        for (int q = 0; q < 4; q++)
            #pragma unroll
            for (int r = 0; r < 8; r++) {
                sa[r] = fmaf(xs[r][d0 + q], wa[q], sa[r]);
                sb[r] = fmaf(xs[r][d0 + q], wb[q], sb[r]);
            }
    }
    #pragma unroll
    for (int r = 0; r < 8; r++) {
        g_ea[(r0 + r) * HID_ + tid] = sa[r];
        g_eb[(r0 + r) * HID_ + tid] = sb[r];
    }
}

// ---------------------------------------------------------------------------
// One 64x256 @ 256x256 tf32-HMMA layer, 8 warps as 2M x 4N, warp tile 32x64.
// ---------------------------------------------------------------------------
template <bool POOL>
__device__ __forceinline__ void run_layer(float* __restrict__ As,
                                          const float* __restrict__ gW,
                                          const float* __restrict__ bias,
                                          float* __restrict__ pooled,
                                          float* __restrict__ Bs, uint32_t bs_u,
                                          int tid, int wm, int wn, int gid, int tig,
                                          int lane) {
    float d[2][8][4];
    #pragma unroll
    for (int mf = 0; mf < 2; mf++)
        #pragma unroll
        for (int nf = 0; nf < 8; nf++)
            #pragma unroll
            for (int q = 0; q < 4; q++) d[mf][nf][q] = 0.f;

    const float4* As4 = (const float4*)As;

    // stage chunk 0 (linear 16KB copy: 1024 float4 / 256 threads)
    {
        const float4* src = (const float4*)gW;
        #pragma unroll
        for (int i = 0; i < 4; i++)
            CP_ASYNC16(bs_u + (uint32_t)(tid + i * 256) * 16u, src + tid + i * 256);
        CP_COMMIT();
    }

    #pragma unroll 1
    for (int kc = 0; kc < NCHUNK; kc++) {
        if (kc < NCHUNK - 1) {
            const float4* src = (const float4*)(gW + (kc + 1) * BUFV);
            uint32_t boff = (uint32_t)(((kc + 1) & 1) * BUFV) * 4u;
            #pragma unroll
            for (int i = 0; i < 4; i++)
                CP_ASYNC16(bs_u + boff + (uint32_t)(tid + i * 256) * 16u, src + tid + i * 256);
            CP_COMMIT();
            CP_WAIT(1);
        } else {
            CP_WAIT(0);
        }
        __syncthreads();

        const float2* Bb2 = (const float2*)(Bs + (kc & 1) * BUFV);
        #pragma unroll
        for (int ks = 0; ks < 2; ks++) {
            const int ct = kc * 2 + ks;                 // global k-tile (k/8), 0..31
            float4 a[2];
            #pragma unroll
            for (int mf = 0; mf < 2; mf++)
                a[mf] = As4[(ct * 4 + wm * 2 + mf) * 32 + lane];
            #pragma unroll
            for (int nf = 0; nf < 8; nf++) {
                float2 bv = Bb2[(ks * 32 + wn * 8 + nf) * 32 + lane];
                uint32_t b0 = __float_as_uint(bv.x);
                uint32_t b1 = __float_as_uint(bv.y);
                mma_tf32(d[0][nf], a[0], b0, b1);
                mma_tf32(d[1][nf], a[1], b0, b1);
            }
        }
        __syncthreads();
    }
    // all reads of As done (barrier above) -> in-place epilogue safe

    if (!POOL) {
        #pragma unroll
        for (int mf = 0; mf < 2; mf++) {
            const int r0 = wm * 32 + mf * 16 + gid;
            #pragma unroll
            for (int nf = 0; nf < 8; nf++) {
                const int c = wn * 64 + nf * 8 + 2 * tig;
                As[scr_off(r0, c)]         = __uint_as_float(tf32_rna(fmaxf(d[mf][nf][0] + bias[c], 0.f)));
                As[scr_off(r0, c + 1)]     = __uint_as_float(tf32_rna(fmaxf(d[mf][nf][1] + bias[c + 1], 0.f)));
                As[scr_off(r0 + 8, c)]     = __uint_as_float(tf32_rna(fmaxf(d[mf][nf][2] + bias[c], 0.f)));
                As[scr_off(r0 + 8, c + 1)] = __uint_as_float(tf32_rna(fmaxf(d[mf][nf][3] + bias[c + 1], 0.f)));
            }
        }
    } else {
        #pragma unroll
        for (int nf = 0; nf < 8; nf++) {
            const int c0 = wn * 64 + nf * 8 + 2 * tig;
            const float bc0 = bias[c0], bc1 = bias[c0 + 1];
            float s0 = 0.f, s1 = 0.f;
            #pragma unroll
            for (int mf = 0; mf < 2; mf++) {
                s0 += fmaxf(d[mf][nf][0] + bc0, 0.f) + fmaxf(d[mf][nf][2] + bc0, 0.f);
                s1 += fmaxf(d[mf][nf][1] + bc1, 0.f) + fmaxf(d[mf][nf][3] + bc1, 0.f);
            }
            #pragma unroll
            for (int off = 4; off < 32; off <<= 1) {
                s0 += __shfl_xor_sync(0xFFFFFFFFu, s0, off);
                s1 += __shfl_xor_sync(0xFFFFFFFFu, s1, off);
            }
            if (gid == 0) {
                atomicAdd(&pooled[c0], s0);
                atomicAdd(&pooled[c0 + 1], s1);
            }
        }
    }
}

// ---------------------------------------------------------------------------
// Main: one CTA per (b,i,half); 64 j-rows; 256 threads; 2 CTAs/SM.
// ---------------------------------------------------------------------------
#define SMEM_FLOATS (64 * HID_ + 2 * BUFV + 5 * HID_)
#define SMEM_DYN    (SMEM_FLOATS * 4)

__global__ void __launch_bounds__(256, 2)
main_kernel(const float* __restrict__ b_enc,
            const float* __restrict__ b1, const float* __restrict__ b2) {
    extern __shared__ float sm[];
    float* A0     = sm;                     // 64*256 scrambled
    float* Bs     = A0 + 64 * HID_;         // 2*BUFV
    float* pooled = Bs + 2 * BUFV;          // 256
    float* ea_s   = pooled + HID_;
    float* sbenc  = ea_s + HID_;
    float* sb1    = sbenc + HID_;
    float* sb2    = sb1 + HID_;

    const int tid  = threadIdx.x;
    const int lane = tid & 31;
    const int w    = tid >> 5;              // 0..7
    const int wm   = w >> 2;                // 0..1 (32-row group)
    const int wn   = w & 3;                 // 0..3 (64-col group)
    const int gid  = lane >> 2;
    const int tig  = lane & 3;
    const int bi2  = blockIdx.x;
    const int bi   = bi2 >> 1;
    const int half = bi2 & 1;
    const int b    = bi >> 7;
    const int j0   = half * 64;
    const uint32_t bs_u = smem_u32(Bs);

    ea_s[tid]   = g_ea[bi * HID_ + tid];
    sbenc[tid]  = b_enc[tid];
    sb1[tid]    = b1[tid];
    sb2[tid]    = b2[tid];
    pooled[tid] = 0.f;
    __syncthreads();

    // ---- build A0 = tf32(relu(ea_i + eb_j + b_enc)), scrambled, 64 rows ----
    const float4* ebr = (const float4*)(g_eb + (b * OBJ_ + j0) * HID_);
    #pragma unroll
    for (int i = 0; i < 16; i++) {
        int idx = tid + i * 256;           // 4096 float4
        int r = idx >> 6, c4 = idx & 63;
        float4 e = ebr[idx];
        int c = c4 * 4;
        int tb = (((c >> 3) << 2) + (r >> 4)) * 128;
        int r16 = r & 15, kk0 = c & 7;     // kk0 in {0,4}
        int base = tb + ((r16 & 7) << 4) + ((kk0 >> 2) << 1) + (r16 >> 3);
        A0[base + 0]  = __uint_as_float(tf32_rna(fmaxf(ea_s[c + 0] + e.x + sbenc[c + 0], 0.f)));
        A0[base + 4]  = __uint_as_float(tf32_rna(fmaxf(ea_s[c + 1] + e.y + sbenc[c + 1], 0.f)));
        A0[base + 8]  = __uint_as_float(tf32_rna(fmaxf(ea_s[c + 2] + e.z + sbenc[c + 2], 0.f)));
        A0[base + 12] = __uint_as_float(tf32_rna(fmaxf(ea_s[c + 3] + e.w + sbenc[c + 3], 0.f)));
    }
    __syncthreads();

    run_layer<false>(A0, g_w12, sb1, pooled, Bs, bs_u, tid, wm, wn, gid, tig, lane);
    __syncthreads();
    run_layer<true>(A0, g_w12 + HID_ * HID_, sb2, pooled, Bs, bs_u,
                    tid, wm, wn, gid, tig, lane);
    __syncthreads();

    g_hpart[(half * ROWS_ + bi) * HID_ + tid] = pooled[tid];
}

// ---------------------------------------------------------------------------
// Dec: hbar = (hpart0 + hpart1)/128; out = relu(hbar @ W34 + b34) @ wd2 + bd2
// ---------------------------------------------------------------------------
#define DEC_HP 257
#define DEC_SMEM_FLOATS (2 * 32 * HID_ + 2 * 4 * DEC_HP + HID_)
#define DEC_SMEM (DEC_SMEM_FLOATS * 4)

__global__ void __launch_bounds__(256) dec_kernel(const float* __restrict__ wd2,
                                                  const float* __restrict__ bd2,
                                                  float* __restrict__ out) {
    extern __shared__ float dsm[];
    float* Wb   = dsm;                       // 2 * 32*256
    float* hb   = Wb + 2 * 32 * HID_;        // 4*DEC_HP
    float* tt   = hb + 4 * DEC_HP;           // 4*DEC_HP
    float* sb34 = tt + 4 * DEC_HP;           // 256

    const int tid = threadIdx.x;
    const int r0 = blockIdx.x * 4;
    const uint32_t wb_u = smem_u32(Wb);

    for (int idx = tid; idx < 4 * HID_; idx += 256) {
        int r = idx >> 8, c = idx & 255;
        hb[r * DEC_HP + c] = (g_hpart[(r0 + r) * HID_ + c] +
                              g_hpart[(ROWS_ + r0 + r) * HID_ + c]) * (1.f / 128.f);
    }
    sb34[tid] = g_b34[tid];
    __syncthreads();

    float a0 = 0.f, a1 = 0.f, a2 = 0.f, a3 = 0.f;
    {
        const float4* src = (const float4*)g_w34;
        #pragma unroll
        for (int i = 0; i < 8; i++)
            CP_ASYNC16(wb_u + (uint32_t)(tid + i * 256) * 16u, src + tid + i * 256);
        CP_COMMIT();
    }
    #pragma unroll 1
    for (int kc = 0; kc < 8; kc++) {
        if (kc < 7) {
            const float4* src = (const float4*)(g_w34 + (kc + 1) * 32 * HID_);
            uint32_t boff = (uint32_t)(((kc + 1) & 1) * 32 * HID_) * 4u;
            #pragma unroll
            for (int i = 0; i < 8; i++)
                CP_ASYNC16(wb_u + boff + (uint32_t)(tid + i * 256) * 16u, src + tid + i * 256);
            CP_COMMIT();
            CP_WAIT(1);
        } else {
            CP_WAIT(0);
        }
        __syncthreads();
        const float* Wc = Wb + (kc & 1) * 32 * HID_;
        const int kb = kc * 32;
        #pragma unroll
        for (int k = 0; k < 32; k++) {
            float wv = Wc[k * HID_ + tid];
            a0 = fmaf(hb[0 * DEC_HP + kb + k], wv, a0);
            a1 = fmaf(hb[1 * DEC_HP + kb + k], wv, a1);
            a2 = fmaf(hb[2 * DEC_HP + kb + k], wv, a2);
            a3 = fmaf(hb[3 * DEC_HP + kb + k], wv, a3);
        }
        __syncthreads();
    }
    tt[0 * DEC_HP + tid] = fmaxf(a0 + sb34[tid], 0.f);
    tt[1 * DEC_HP + tid] = fmaxf(a1 + sb34[tid], 0.f);
    tt[2 * DEC_HP + tid] = fmaxf(a2 + sb34[tid], 0.f);
    tt[3 * DEC_HP + tid] = fmaxf(a3 + sb34[tid], 0.f);
    __syncthreads();

    const int c = tid & 63, rr = tid >> 6;
    const float* trow = tt + rr * DEC_HP;
    float o = 0.f;
    float wv[8];
    #pragma unroll
    for (int q = 0; q < 8; q++) wv[q] = wd2[q * INP_ + c];
    #pragma unroll 1
    for (int k0 = 0; k0 < HID_; k0 += 8) {
        float wnx[8];
        if (k0 + 8 < HID_) {
            #pragma unroll
            for (int q = 0; q < 8; q++) wnx[q] = wd2[(k0 + 8 + q) * INP_ + c];
        }
        #pragma unroll
        for (int q = 0; q < 8; q++) o = fmaf(trow[k0 + q], wv[q], o);
        #pragma unroll
        for (int q = 0; q < 8; q++) wv[q] = wnx[q];
    }
    out[(r0 + rr) * INP_ + c] = o + bd2[c];
}

// ---------------------------------------------------------------------------
extern "C" void kernel_launch(void* const* d_in, const int* in_sizes, int n_in,
                              void* d_out, int out_size) {
    const float* x0    = (const float*)d_in[0];
    const float* x1    = (const float*)d_in[1];
    const float* x2    = (const float*)d_in[2];
    const float* w_enc = (const float*)d_in[3];
    const float* b_enc = (const float*)d_in[4];
    const float* w1    = (const float*)d_in[5];
    const float* b1    = (const float*)d_in[6];
    const float* w2    = (const float*)d_in[7];
    const float* b2    = (const float*)d_in[8];
    const float* w3    = (const float*)d_in[9];
    const float* b3    = (const float*)d_in[10];
    const float* wd1   = (const float*)d_in[11];
    const float* bd1   = (const float*)d_in[12];
    const float* wd2   = (const float*)d_in[13];
    const float* bd2   = (const float*)d_in[14];
    float* out = (float*)d_out;

    cudaFuncSetAttribute(main_kernel,
                         cudaFuncAttributeMaxDynamicSharedMemorySize, SMEM_DYN);
    cudaFuncSetAttribute(dec_kernel,
                         cudaFuncAttributeMaxDynamicSharedMemorySize, DEC_SMEM);

    pre_kernel<<<641, 256>>>(x0, x1, x2, w_enc, w1, w2, w3, b3, wd1, bd1);
    main_kernel<<<2 * ROWS_, 256, SMEM_DYN>>>(b_enc, b1, b2);
    dec_kernel<<<ROWS_ / 4, 256, DEC_SMEM>>>(wd2, bd2, out);
}

// round 11
// speedup vs baseline: 1.0432x; 1.0432x over previous
#include <cuda_runtime.h>
#include <cstdint>

#define B_   8
#define OBJ_ 128
#define INP_ 64
#define HID_ 256
#define D_   192
#define ROWS_ (B_*OBJ_)   // 1024

// ---------------- device scratch (allocation-free) ----------------
__device__ __align__(256) float g_ea[ROWS_ * HID_];
__device__ __align__(256) float g_eb[ROWS_ * HID_];
__device__ __align__(256) float g_hbar[ROWS_ * HID_];     // mean_j relu(H2)
__device__ __align__(256) float g_w12[2 * HID_ * HID_];   // tf32, frag-scrambled W1,W2
__device__ __align__(256) float g_w34[HID_ * HID_];       // w3 @ wd1 (fp32)
__device__ __align__(256) float g_b34[HID_];              // b3 @ wd1 + bd1

// ---------------- helpers ----------------
__device__ __forceinline__ uint32_t smem_u32(const void* p) {
    uint32_t a;
    asm("{ .reg .u64 t; cvta.to.shared.u64 t, %1; cvt.u32.u64 %0, t; }" : "=r"(a) : "l"(p));
    return a;
}
__device__ __forceinline__ uint32_t tf32_rna(float f) {
    uint32_t r;
    asm("cvt.rna.tf32.f32 %0, %1;" : "=r"(r) : "f"(f));
    return r;
}
__device__ __forceinline__ void mma_tf32(float d[4], const float4 a, uint32_t b0, uint32_t b1) {
    asm volatile(
        "mma.sync.aligned.m16n8k8.row.col.f32.tf32.tf32.f32 "
        "{%0,%1,%2,%3}, {%4,%5,%6,%7}, {%8,%9}, {%0,%1,%2,%3};"
        : "+f"(d[0]), "+f"(d[1]), "+f"(d[2]), "+f"(d[3])
        : "r"(__float_as_uint(a.x)), "r"(__float_as_uint(a.y)),
          "r"(__float_as_uint(a.z)), "r"(__float_as_uint(a.w)),
          "r"(b0), "r"(b1));
}
#define CP_ASYNC16(dst, src) \
    asm volatile("cp.async.cg.shared.global [%0], [%1], 16;" :: "r"(dst), "l"(src))
#define CP_COMMIT() asm volatile("cp.async.commit_group;" ::: "memory")
#define CP_WAIT(n)  asm volatile("cp.async.wait_group %0;" :: "n"(n) : "memory")

// A scrambled layout (128 rows): 16(row)x8(k) tiles of 128 floats;
// tile id = (k/8)*8 + (r/16); pos = ((r16&7)*4+(kk&3))*4 + (kk>>2)*2 + (r16>>3)
__device__ __forceinline__ int scr_pos(int r16, int kk) {
    return (((r16 & 7) << 2) + (kk & 3)) * 4 + ((kk >> 2) << 1) + (r16 >> 3);
}
__device__ __forceinline__ int scr_off(int r, int c) {
    return (((c >> 3) << 3) + (r >> 4)) * 128 + scr_pos(r & 15, c & 7);
}

#define BUFV (32 * HID_)    // one 32-k-row scrambled weight chunk (floats)

// ---------------------------------------------------------------------------
// Fused pre-kernel: [0,256) W1/W2 tf32-scramble; [256,384) encoder.
// W layout: chunk kc (32 k-rows): off = kc*8192 + (tk4*32 + tn)*64 + pos
// ---------------------------------------------------------------------------
__global__ void __launch_bounds__(256) pre_kernel(
    const float* __restrict__ x0, const float* __restrict__ x1,
    const float* __restrict__ x2, const float* __restrict__ w_enc,
    const float* __restrict__ w1, const float* __restrict__ w2) {
    __shared__ float xs[8][D_];
    const int bid = blockIdx.x;
    const int tid = threadIdx.x;

    if (bid < 256) {
        int idx = bid * 256 + tid;             // k*256+n
        int k = idx >> 8, n = idx & 255;
        int kc = k >> 5, tk4 = (k >> 3) & 3, tn = n >> 3;
        int kk = k & 7, nn = n & 7;
        int pos = ((nn << 2) + (kk & 3)) * 2 + (kk >> 2);
        int off = kc * 8192 + (tk4 * 32 + tn) * 64 + pos;
        g_w12[off]               = __uint_as_float(tf32_rna(w1[idx]));
        g_w12[HID_ * HID_ + off] = __uint_as_float(tf32_rna(w2[idx]));
        return;
    }
    // encoder: 8 rows per CTA
    const int r0 = (bid - 256) * 8;
    for (int idx = tid; idx < 8 * D_; idx += 256) {
        int r = idx / D_, d = idx % D_;
        int part = d >> 6, dd = d & 63;
        const float* src = (part == 0) ? x0 : ((part == 1) ? x1 : x2);
        xs[r][d] = src[(r0 + r) * INP_ + dd];
    }
    __syncthreads();
    float sa[8], sb[8];
    #pragma unroll
    for (int r = 0; r < 8; r++) { sa[r] = 0.f; sb[r] = 0.f; }
    #pragma unroll 1
    for (int d0 = 0; d0 < D_; d0 += 4) {
        float wa[4], wb[4];
        #pragma unroll
        for (int q = 0; q < 4; q++) {
            wa[q] = w_enc[(d0 + q) * HID_ + tid];
            wb[q] = w_enc[(D_ + d0 + q) * HID_ + tid];
        }
        #pragma unroll
        for (int q = 0; q < 4; q++)
            #pragma unroll
            for (int r = 0; r < 8; r++) {
                sa[r] = fmaf(xs[r][d0 + q], wa[q], sa[r]);
                sb[r] = fmaf(xs[r][d0 + q], wb[q], sb[r]);
            }
    }
    #pragma unroll
    for (int r = 0; r < 8; r++) {
        g_ea[(r0 + r) * HID_ + tid] = sa[r];
        g_eb[(r0 + r) * HID_ + tid] = sb[r];
    }
}

// ---------------------------------------------------------------------------
// W34 mini-GEMM: W34 = w3 @ wd1 (+ bias row). 17 CTAs x 16 rows (CTA 16 = bias).
// wd1 streamed via cp.async double buffer; w3 rows resident in smem.
// ---------------------------------------------------------------------------
#define W34_SMEM ((16 * HID_ + 2 * 32 * HID_) * 4)   // 16KB + 64KB

template <int NR>
__device__ __forceinline__ void w34_body(const float* __restrict__ w3s,
                                         const float* __restrict__ wd1,
                                         float* __restrict__ Wb, uint32_t wb_u,
                                         int tid, float* acc) {
    {
        const float4* src = (const float4*)wd1;
        #pragma unroll
        for (int i = 0; i < 8; i++)
            CP_ASYNC16(wb_u + (uint32_t)(tid + i * 256) * 16u, src + tid + i * 256);
        CP_COMMIT();
    }
    #pragma unroll 1
    for (int kc = 0; kc < 8; kc++) {
        if (kc < 7) {
            const float4* src = (const float4*)(wd1 + (kc + 1) * 32 * HID_);
            uint32_t boff = (uint32_t)(((kc + 1) & 1) * 32 * HID_) * 4u;
            #pragma unroll
            for (int i = 0; i < 8; i++)
                CP_ASYNC16(wb_u + boff + (uint32_t)(tid + i * 256) * 16u, src + tid + i * 256);
            CP_COMMIT();
            CP_WAIT(1);
        } else {
            CP_WAIT(0);
        }
        __syncthreads();
        const float* Wc = Wb + (kc & 1) * 32 * HID_;
        const int kb = kc * 32;
        #pragma unroll
        for (int k = 0; k < 32; k++) {
            float wv = Wc[k * HID_ + tid];
            #pragma unroll
            for (int r = 0; r < NR; r++)
                acc[r] = fmaf(w3s[r * HID_ + kb + k], wv, acc[r]);
        }
        __syncthreads();
    }
}

__global__ void __launch_bounds__(256) w34_kernel(const float* __restrict__ w3,
                                                  const float* __restrict__ b3,
                                                  const float* __restrict__ wd1,
                                                  const float* __restrict__ bd1) {
    extern __shared__ float wsm[];
    float* w3s = wsm;                 // 16*256
    float* Wb  = wsm + 16 * HID_;     // 2*32*256
    const int bid = blockIdx.x;
    const int tid = threadIdx.x;
    const uint32_t wb_u = smem_u32(Wb);

    if (bid < 16) {
        const int m0 = bid * 16;
        for (int idx = tid; idx < 16 * HID_; idx += 256)
            w3s[idx] = w3[m0 * HID_ + idx];
        __syncthreads();
        float acc[16];
        #pragma unroll
        for (int r = 0; r < 16; r++) acc[r] = 0.f;
        w34_body<16>(w3s, wd1, Wb, wb_u, tid, acc);
        #pragma unroll
        for (int r = 0; r < 16; r++)
            g_w34[(m0 + r) * HID_ + tid] = acc[r];
    } else {
        w3s[tid] = b3[tid];
        __syncthreads();
        float acc[1] = {0.f};
        w34_body<1>(w3s, wd1, Wb, wb_u, tid, acc);
        g_b34[tid] = acc[0] + bd1[tid];
    }
}

// ---------------------------------------------------------------------------
// One 128x256 @ 256x256 tf32-HMMA layer, 16 warps as 2M x 8N, warp tile 64x32.
// Fragment-native layouts: A-frag = 1 LDS.128, B-frag = 1 LDS.64.
// ---------------------------------------------------------------------------
template <bool POOL>
__device__ __forceinline__ void run_layer(float* __restrict__ As,
                                          const float* __restrict__ gW,
                                          const float* __restrict__ bias,
                                          float* __restrict__ pooled,
                                          float* __restrict__ Bs, uint32_t bs_u,
                                          int tid, int wm, int wn, int gid, int tig,
                                          int lane) {
    float d[4][4][4];
    #pragma unroll
    for (int mf = 0; mf < 4; mf++)
        #pragma unroll
        for (int nf = 0; nf < 4; nf++)
            #pragma unroll
            for (int q = 0; q < 4; q++) d[mf][nf][q] = 0.f;

    const float4* As4 = (const float4*)As;

    // stage chunk 0 (linear 32KB copy)
    {
        const float4* src = (const float4*)gW;
        #pragma unroll
        for (int i = 0; i < 4; i++)
            CP_ASYNC16(bs_u + (uint32_t)(tid + i * 512) * 16u, src + tid + i * 512);
        CP_COMMIT();
    }

    #pragma unroll 1
    for (int kc = 0; kc < 8; kc++) {
        if (kc < 7) {
            const float4* src = (const float4*)(gW + (kc + 1) * BUFV);
            uint32_t boff = (uint32_t)(((kc + 1) & 1) * BUFV) * 4u;
            #pragma unroll
            for (int i = 0; i < 4; i++)
                CP_ASYNC16(bs_u + boff + (uint32_t)(tid + i * 512) * 16u, src + tid + i * 512);
            CP_COMMIT();
            CP_WAIT(1);
        } else {
            CP_WAIT(0);
        }
        __syncthreads();

        const float2* Bb2 = (const float2*)(Bs + (kc & 1) * BUFV);
        #pragma unroll
        for (int ks = 0; ks < 4; ks++) {
            const int ct = kc * 4 + ks;                 // k-tile id (k/8)
            float4 a[4];
            #pragma unroll
            for (int mf = 0; mf < 4; mf++)
                a[mf] = As4[(ct * 8 + wm * 4 + mf) * 32 + lane];
            #pragma unroll
            for (int nf = 0; nf < 4; nf++) {
                float2 bv = Bb2[(ks * 32 + wn * 4 + nf) * 32 + lane];
                uint32_t b0 = __float_as_uint(bv.x);
                uint32_t b1 = __float_as_uint(bv.y);
                #pragma unroll
                for (int mf = 0; mf < 4; mf++)
                    mma_tf32(d[mf][nf], a[mf], b0, b1);
            }
        }
        __syncthreads();
    }
    // all reads of As done (barrier above) -> in-place epilogue safe

    if (!POOL) {
        #pragma unroll
        for (int mf = 0; mf < 4; mf++) {
            const int r0 = wm * 64 + mf * 16 + gid;
            #pragma unroll
            for (int nf = 0; nf < 4; nf++) {
                const int c = wn * 32 + nf * 8 + 2 * tig;
                As[scr_off(r0, c)]         = __uint_as_float(tf32_rna(fmaxf(d[mf][nf][0] + bias[c], 0.f)));
                As[scr_off(r0, c + 1)]     = __uint_as_float(tf32_rna(fmaxf(d[mf][nf][1] + bias[c + 1], 0.f)));
                As[scr_off(r0 + 8, c)]     = __uint_as_float(tf32_rna(fmaxf(d[mf][nf][2] + bias[c], 0.f)));
                As[scr_off(r0 + 8, c + 1)] = __uint_as_float(tf32_rna(fmaxf(d[mf][nf][3] + bias[c + 1], 0.f)));
            }
        }
    } else {
        #pragma unroll
        for (int nf = 0; nf < 4; nf++) {
            const int c0 = wn * 32 + nf * 8 + 2 * tig;
            const float bc0 = bias[c0], bc1 = bias[c0 + 1];
            float s0 = 0.f, s1 = 0.f;
            #pragma unroll
            for (int mf = 0; mf < 4; mf++) {
                s0 += fmaxf(d[mf][nf][0] + bc0, 0.f) + fmaxf(d[mf][nf][2] + bc0, 0.f);
                s1 += fmaxf(d[mf][nf][1] + bc1, 0.f) + fmaxf(d[mf][nf][3] + bc1, 0.f);
            }
            #pragma unroll
            for (int off = 4; off < 32; off <<= 1) {
                s0 += __shfl_xor_sync(0xFFFFFFFFu, s0, off);
                s1 += __shfl_xor_sync(0xFFFFFFFFu, s1, off);
            }
            if (gid == 0) {
                atomicAdd(&pooled[c0], s0);
                atomicAdd(&pooled[c0 + 1], s1);
            }
        }
    }
}

// ---------------------------------------------------------------------------
// Main: one CTA per (b,i); single pass over 128 j-rows; 512 threads.
// ---------------------------------------------------------------------------
#define SMEM_FLOATS (128 * HID_ + 2 * BUFV + 5 * HID_)
#define SMEM_DYN    (SMEM_FLOATS * 4)

__global__ void __launch_bounds__(512, 1)
main_kernel(const float* __restrict__ b_enc,
            const float* __restrict__ b1, const float* __restrict__ b2) {
    extern __shared__ float sm[];
    float* A0     = sm;                     // 128*256 scrambled
    float* Bs     = A0 + 128 * HID_;        // 2*BUFV
    float* pooled = Bs + 2 * BUFV;          // 256
    float* ea_s   = pooled + HID_;
    float* sbenc  = ea_s + HID_;
    float* sb1    = sbenc + HID_;
    float* sb2    = sb1 + HID_;

    const int tid  = threadIdx.x;
    const int lane = tid & 31;
    const int w    = tid >> 5;              // 0..15
    const int wm   = w >> 3;                // 0..1 (64-row group)
    const int wn   = w & 7;                 // 0..7 (32-col group)
    const int gid  = lane >> 2;
    const int tig  = lane & 3;
    const int bi   = blockIdx.x;
    const int b    = bi >> 7;
    const uint32_t bs_u = smem_u32(Bs);

    if (tid < 256) {
        ea_s[tid]   = g_ea[bi * HID_ + tid];
        sbenc[tid]  = b_enc[tid];
        sb1[tid]    = b1[tid];
        sb2[tid]    = b2[tid];
        pooled[tid] = 0.f;
    }
    __syncthreads();

    // ---- build A0 = tf32(relu(ea_i + eb_j + b_enc)), scrambled ----
    const float4* ebr = (const float4*)(g_eb + (b * OBJ_) * HID_);
    #pragma unroll
    for (int i = 0; i < 16; i++) {
        int idx = tid + i * 512;           // 8192 float4
        int r = idx >> 6, c4 = idx & 63;
        float4 e = ebr[idx];
        int c = c4 * 4;
        int tb = (((c >> 3) << 3) + (r >> 4)) * 128;
        int r16 = r & 15, kk0 = c & 7;     // kk0 in {0,4}
        int base = tb + ((r16 & 7) << 4) + ((kk0 >> 2) << 1) + (r16 >> 3);
        A0[base + 0]  = __uint_as_float(tf32_rna(fmaxf(ea_s[c + 0] + e.x + sbenc[c + 0], 0.f)));
        A0[base + 4]  = __uint_as_float(tf32_rna(fmaxf(ea_s[c + 1] + e.y + sbenc[c + 1], 0.f)));
        A0[base + 8]  = __uint_as_float(tf32_rna(fmaxf(ea_s[c + 2] + e.z + sbenc[c + 2], 0.f)));
        A0[base + 12] = __uint_as_float(tf32_rna(fmaxf(ea_s[c + 3] + e.w + sbenc[c + 3], 0.f)));
    }
    __syncthreads();

    run_layer<false>(A0, g_w12, sb1, pooled, Bs, bs_u, tid, wm, wn, gid, tig, lane);
    __syncthreads();
    run_layer<true>(A0, g_w12 + HID_ * HID_, sb2, pooled, Bs, bs_u,
                    tid, wm, wn, gid, tig, lane);
    __syncthreads();

    if (tid < 256)
        g_hbar[bi * HID_ + tid] = pooled[tid] * (1.f / 128.f);
}

// ---------------------------------------------------------------------------
// Dec: out = relu(hbar @ W34 + b34) @ wd2 + bd2
// ---------------------------------------------------------------------------
#define DEC_HP 257
#define DEC_SMEM_FLOATS (2 * 32 * HID_ + 2 * 4 * DEC_HP + HID_)
#define DEC_SMEM (DEC_SMEM_FLOATS * 4)

__global__ void __launch_bounds__(256) dec_kernel(const float* __restrict__ wd2,
                                                  const float* __restrict__ bd2,
                                                  float* __restrict__ out) {
    extern __shared__ float dsm[];
    float* Wb   = dsm;                       // 2 * 32*256
    float* hb   = Wb + 2 * 32 * HID_;        // 4*DEC_HP
    float* tt   = hb + 4 * DEC_HP;           // 4*DEC_HP
    float* sb34 = tt + 4 * DEC_HP;           // 256

    const int tid = threadIdx.x;
    const int r0 = blockIdx.x * 4;
    const uint32_t wb_u = smem_u32(Wb);

    for (int idx = tid; idx < 4 * HID_; idx += 256)
        hb[(idx >> 8) * DEC_HP + (idx & 255)] = g_hbar[(r0 + (idx >> 8)) * HID_ + (idx & 255)];
    sb34[tid] = g_b34[tid];
    __syncthreads();

    float a0 = 0.f, a1 = 0.f, a2 = 0.f, a3 = 0.f;
    {
        const float4* src = (const float4*)g_w34;
        #pragma unroll
        for (int i = 0; i < 8; i++)
            CP_ASYNC16(wb_u + (uint32_t)(tid + i * 256) * 16u, src + tid + i * 256);
        CP_COMMIT();
    }
    #pragma unroll 1
    for (int kc = 0; kc < 8; kc++) {
        if (kc < 7) {
            const float4* src = (const float4*)(g_w34 + (kc + 1) * 32 * HID_);
            uint32_t boff = (uint32_t)(((kc + 1) & 1) * 32 * HID_) * 4u;
            #pragma unroll
            for (int i = 0; i < 8; i++)
                CP_ASYNC16(wb_u + boff + (uint32_t)(tid + i * 256) * 16u, src + tid + i * 256);
            CP_COMMIT();
            CP_WAIT(1);
        } else {
            CP_WAIT(0);
        }
        __syncthreads();
        const float* Wc = Wb + (kc & 1) * 32 * HID_;
        const int kb = kc * 32;
        #pragma unroll
        for (int k = 0; k < 32; k++) {
            float wv = Wc[k * HID_ + tid];
            a0 = fmaf(hb[0 * DEC_HP + kb + k], wv, a0);
            a1 = fmaf(hb[1 * DEC_HP + kb + k], wv, a1);
            a2 = fmaf(hb[2 * DEC_HP + kb + k], wv, a2);
            a3 = fmaf(hb[3 * DEC_HP + kb + k], wv, a3);
        }
        __syncthreads();
    }
    tt[0 * DEC_HP + tid] = fmaxf(a0 + sb34[tid], 0.f);
    tt[1 * DEC_HP + tid] = fmaxf(a1 + sb34[tid], 0.f);
    tt[2 * DEC_HP + tid] = fmaxf(a2 + sb34[tid], 0.f);
    tt[3 * DEC_HP + tid] = fmaxf(a3 + sb34[tid], 0.f);
    __syncthreads();

    const int c = tid & 63, rr = tid >> 6;
    const float* trow = tt + rr * DEC_HP;
    float o = 0.f;
    float wv[8];
    #pragma unroll
    for (int q = 0; q < 8; q++) wv[q] = wd2[q * INP_ + c];
    #pragma unroll 1
    for (int k0 = 0; k0 < HID_; k0 += 8) {
        float wnx[8];
        if (k0 + 8 < HID_) {
            #pragma unroll
            for (int q = 0; q < 8; q++) wnx[q] = wd2[(k0 + 8 + q) * INP_ + c];
        }
        #pragma unroll
        for (int q = 0; q < 8; q++) o = fmaf(trow[k0 + q], wv[q], o);
        #pragma unroll
        for (int q = 0; q < 8; q++) wv[q] = wnx[q];
    }
    out[(r0 + rr) * INP_ + c] = o + bd2[c];
}

// ---------------------------------------------------------------------------
extern "C" void kernel_launch(void* const* d_in, const int* in_sizes, int n_in,
                              void* d_out, int out_size) {
    const float* x0    = (const float*)d_in[0];
    const float* x1    = (const float*)d_in[1];
    const float* x2    = (const float*)d_in[2];
    const float* w_enc = (const float*)d_in[3];
    const float* b_enc = (const float*)d_in[4];
    const float* w1    = (const float*)d_in[5];
    const float* b1    = (const float*)d_in[6];
    const float* w2    = (const float*)d_in[7];
    const float* b2    = (const float*)d_in[8];
    const float* w3    = (const float*)d_in[9];
    const float* b3    = (const float*)d_in[10];
    const float* wd1   = (const float*)d_in[11];
    const float* bd1   = (const float*)d_in[12];
    const float* wd2   = (const float*)d_in[13];
    const float* bd2   = (const float*)d_in[14];
    float* out = (float*)d_out;

    cudaFuncSetAttribute(main_kernel,
                         cudaFuncAttributeMaxDynamicSharedMemorySize, SMEM_DYN);
    cudaFuncSetAttribute(dec_kernel,
                         cudaFuncAttributeMaxDynamicSharedMemorySize, DEC_SMEM);
    cudaFuncSetAttribute(w34_kernel,
                         cudaFuncAttributeMaxDynamicSharedMemorySize, W34_SMEM);

    pre_kernel<<<384, 256>>>(x0, x1, x2, w_enc, w1, w2);
    w34_kernel<<<17, 256, W34_SMEM>>>(w3, b3, wd1, bd1);
    main_kernel<<<ROWS_, 512, SMEM_DYN>>>(b_enc, b1, b2);
    dec_kernel<<<ROWS_ / 4, 256, DEC_SMEM>>>(wd2, bd2, out);
}